// round 16
// baseline (speedup 1.0000x reference)
#include <cuda_runtime.h>
#include <cuda_fp16.h>
#include <math.h>
#include <stdint.h>

#define B_     8
#define C_     192
#define HEADS_ 8
#define HD_    24
#define HW_    128
#define NPIX_  16384
#define C3_    576
#define K_     192

// GEMM tiling: 1-pass fp16, CTA 128x256, warp tile 64x64, single-buffered A
#define BN_ 256
#define BMq_ 128
#define BT_ROW_ 400
#define BTILE_ (BN_ * BT_ROW_)     // 102400
#define ATILE_ (BMq_ * BT_ROW_)    // 51200
#define SM_GEMM_ (BTILE_ + ATILE_) // 153600

// gram
#define GSLICES_ 16
#define GROW_ 132
#define GSM_GRAM_ (4 * 2 * HD_ * GROW_ * 4)

// ---------------- scratch ----------------
__device__ __half g_qkv [(size_t)B_ * C3_ * NPIX_];
__device__ __half g_qkv2[(size_t)B_ * C3_ * NPIX_];
__device__ float g_gates[(size_t)B_ * HEADS_ * NPIX_];
__device__ float g_ss  [B_ * 2 * C_ * 2];
__device__ float g_gram_part[(size_t)B_ * HEADS_ * GSLICES_ * HD_ * HD_];
__device__ float g_attn [B_ * HEADS_ * HD_ * HD_];
__device__ __half g_xt  [(size_t)B_ * NPIX_ * K_];
__device__ __half g_ot  [(size_t)B_ * NPIX_ * K_];
__device__ __half g_wq  [640 * K_];   // padded, zeros beyond 576
__device__ __half g_wp  [256 * K_];   // padded, zeros beyond 192

// ---------------- helpers ----------------
__device__ __forceinline__ uint32_t smem_u32(const void* p) {
    uint32_t a;
    asm("{ .reg .u64 t; cvta.to.shared.u64 t, %1; cvt.u32.u64 %0, t; }" : "=r"(a) : "l"(p));
    return a;
}
__device__ __forceinline__ void cp16(uint32_t d, const void* s) {
    asm volatile("cp.async.cg.shared.global [%0], [%1], 16;" :: "r"(d), "l"(s));
}
#define CP_COMMIT() asm volatile("cp.async.commit_group;" ::: "memory")
#define CP_WAIT(n)  asm volatile("cp.async.wait_group %0;" :: "n"(n) : "memory")
__device__ __forceinline__ void ldm_x4(uint32_t& r0, uint32_t& r1, uint32_t& r2, uint32_t& r3, uint32_t a) {
    asm volatile("ldmatrix.sync.aligned.m8n8.x4.shared.b16 {%0,%1,%2,%3}, [%4];"
                 : "=r"(r0), "=r"(r1), "=r"(r2), "=r"(r3) : "r"(a));
}
__device__ __forceinline__ void mma16816(float* c, uint32_t a0, uint32_t a1, uint32_t a2, uint32_t a3,
                                         uint32_t b0, uint32_t b1) {
    asm volatile("mma.sync.aligned.m16n8k16.row.col.f32.f16.f16.f32 "
                 "{%0,%1,%2,%3}, {%4,%5,%6,%7}, {%8,%9}, {%0,%1,%2,%3};"
                 : "+f"(c[0]), "+f"(c[1]), "+f"(c[2]), "+f"(c[3])
                 : "r"(a0), "r"(a1), "r"(a2), "r"(a3), "r"(b0), "r"(b1));
}
__device__ __forceinline__ void h8_to_f8(uint4 raw, float4& lo, float4& hi) {
    const __half2* hp = (const __half2*)&raw;
    float2 f0 = __half22float2(hp[0]);
    float2 f1 = __half22float2(hp[1]);
    float2 f2 = __half22float2(hp[2]);
    float2 f3 = __half22float2(hp[3]);
    lo = make_float4(f0.x, f0.y, f1.x, f1.y);
    hi = make_float4(f2.x, f2.y, f3.x, f3.y);
}

// ---------------- convert fp32 -> fp16 weights with zero pad ----------------
__global__ void conv_w_kernel(const float* __restrict__ w, __half* __restrict__ o,
                              int total, int padded) {
    int i = blockIdx.x * 256 + threadIdx.x;
    if (i >= padded) return;
    o[i] = (i < total) ? __float2half(w[i]) : __float2half(0.f);
}

// ---------------- fused: transpose x (fp16, vectorized) AND router gates ----------------
__global__ void fused_tr_router(const float* __restrict__ x,
                                const float* __restrict__ rw_main,
                                const float* __restrict__ rw_aux,
                                const int*   __restrict__ task_id,
                                __half* __restrict__ xt,
                                float* __restrict__ gates) {
    int b = blockIdx.y;
    int n0 = blockIdx.x * 32;
    __shared__ float tile[C_][33];
    __shared__ float w[HEADS_ * C_];
    __shared__ float sg[HEADS_][32];
    int t = threadIdx.x;
    const float* rw = (task_id[0] == 0) ? rw_main : rw_aux;
    for (int i = t; i < HEADS_ * C_; i += 256) w[i] = rw[i];
    for (int i = t; i < C_ * 32; i += 256) {
        int c = i >> 5, j = i & 31;
        tile[c][j] = x[((size_t)b * C_ + c) * NPIX_ + n0 + j];
    }
    __syncthreads();

    for (int i = t; i < 32 * 24; i += 256) {
        int j = i / 24, c8 = i - j * 24;
        __half hv[8];
#pragma unroll
        for (int q = 0; q < 8; q++) hv[q] = __float2half(tile[c8 * 8 + q][j]);
        *(uint4*)(xt + ((size_t)b * NPIX_ + n0 + j) * K_ + c8 * 8) = *(uint4*)hv;
    }

    int j = t >> 3, k = t & 7;
    float lg[HEADS_];
#pragma unroll
    for (int h = 0; h < HEADS_; h++) lg[h] = 0.f;
#pragma unroll
    for (int i = 0; i < 24; i++) {
        int c = k + i * 8;
        float xv = tile[c][j];
#pragma unroll
        for (int h = 0; h < HEADS_; h++) lg[h] += xv * w[h * C_ + c];
    }
#pragma unroll
    for (int h = 0; h < HEADS_; h++) {
        lg[h] += __shfl_down_sync(0xffffffffu, lg[h], 4, 8);
        lg[h] += __shfl_down_sync(0xffffffffu, lg[h], 2, 8);
        lg[h] += __shfl_down_sync(0xffffffffu, lg[h], 1, 8);
    }
    if (k == 0) {
        float mx = lg[0];
#pragma unroll
        for (int h = 1; h < HEADS_; h++) mx = fmaxf(mx, lg[h]);
        float p[HEADS_]; float s = 0.f;
#pragma unroll
        for (int h = 0; h < HEADS_; h++) { p[h] = expf(lg[h] - mx); s += p[h]; }
        float inv = 1.f / s;
#pragma unroll
        for (int h = 0; h < HEADS_; h++) p[h] *= inv;
        int h1 = 0;
#pragma unroll
        for (int h = 1; h < HEADS_; h++) if (p[h] > p[h1]) h1 = h;
        int h2 = -1;
#pragma unroll
        for (int h = 0; h < HEADS_; h++) if (h != h1 && (h2 < 0 || p[h] > p[h2])) h2 = h;
        float denom = fmaxf(p[h1] + p[h2], 1.1920929e-07f);
        float gscale = 2.0f / denom;
#pragma unroll
        for (int h = 0; h < HEADS_; h++)
            sg[h][j] = (h == h1) ? p[h1] * gscale : ((h == h2) ? p[h2] * gscale : 0.f);
    }
    __syncthreads();
    {
        int h = t >> 5, jj = t & 31;
        gates[((size_t)b * HEADS_ + h) * NPIX_ + n0 + jj] = sg[h][jj];
    }
}

// ---------------- HMMA fp16 1-pass GEMM: CTA 128x256, warp tile 64x64 ----------------
template<typename TOut>
__global__ void __launch_bounds__(256, 1)
gemm_mma(const __half* __restrict__ A,
         const __half* __restrict__ Bx,
         TOut* __restrict__ Y, int mtiles, int Mvalid) {
    extern __shared__ char dsm[];
    uint32_t sb = smem_u32(dsm);
    uint32_t uB = sb;
    uint32_t uA = sb + BTILE_;

    int t = threadIdx.x, wid = t >> 5, lane = t & 31;
    int n0 = blockIdx.x * BN_;
    int b  = blockIdx.z;
    Y += (size_t)b * Mvalid * NPIX_;

    // B tile once: 256 rows x 24 chunks
    const char* pB = (const char*)(Bx + ((size_t)b * NPIX_ + n0) * K_);
    for (int i = t; i < 6144; i += 256) {
        int r = i / 24, ck = i - r * 24;
        cp16(uB + r * BT_ROW_ + ck * 16, pB + i * 16);
    }
    CP_COMMIT();

    // 8 warps: 2 (M) x 4 (N); warp tile 64 x 64
    int wm = wid >> 2, wn = wid & 3;
    int mBase = wm * 64;
    int nBase = wn * 64;
    uint32_t aRowOff = (mBase + (lane & 15)) * BT_ROW_ + (lane >> 4) * 16;
    uint32_t bAddr4 = (nBase + ((lane >> 4) & 1) * 8 + (lane & 7)) * BT_ROW_ + ((lane >> 3) & 1) * 16;
    int grp = lane >> 2, tig = lane & 3;

    for (int mt = 0; mt < mtiles; mt++) {
        int m0 = mt * BMq_;
        __syncthreads();   // A smem free
        // load A tile mt: 128 rows x 24 chunks (weights zero-padded)
        for (int i = t; i < 3072; i += 256) {
            int r = i / 24, ck = i - r * 24;
            cp16(uA + r * BT_ROW_ + ck * 16, A + (size_t)(m0 + r) * K_ + ck * 8);
        }
        CP_COMMIT();
        CP_WAIT(0);
        __syncthreads();

        bool okm[4];
#pragma unroll
        for (int mi = 0; mi < 4; mi++) okm[mi] = (m0 + mBase + mi * 16) < Mvalid;

        float acc[4][8][4];
#pragma unroll
        for (int mi = 0; mi < 4; mi++)
#pragma unroll
            for (int ni = 0; ni < 8; ni++)
#pragma unroll
                for (int jj = 0; jj < 4; jj++) acc[mi][ni][jj] = 0.f;

#pragma unroll
        for (int kc = 0; kc < 12; kc++) {
            uint32_t kByte = kc * 32;
            uint32_t ah[4][4], bh[8][2];
#pragma unroll
            for (int mi = 0; mi < 4; mi++) {
                if (okm[mi]) {
                    uint32_t o = aRowOff + mi * (16 * BT_ROW_) + kByte;
                    ldm_x4(ah[mi][0], ah[mi][1], ah[mi][2], ah[mi][3], uA + o);
                }
            }
#pragma unroll
            for (int pr = 0; pr < 4; pr++) {
                uint32_t o = bAddr4 + pr * (16 * BT_ROW_) + kByte;
                ldm_x4(bh[pr*2][0], bh[pr*2][1], bh[pr*2+1][0], bh[pr*2+1][1], uB + o);
            }
#pragma unroll
            for (int mi = 0; mi < 4; mi++) {
                if (okm[mi]) {
#pragma unroll
                    for (int ni = 0; ni < 8; ni++)
                        mma16816(acc[mi][ni], ah[mi][0], ah[mi][1], ah[mi][2], ah[mi][3], bh[ni][0], bh[ni][1]);
                }
            }
        }

#pragma unroll
        for (int mi = 0; mi < 4; mi++) {
            if (!okm[mi]) continue;
            int r0 = m0 + mBase + mi * 16 + grp;
            int r1 = r0 + 8;
#pragma unroll
            for (int ni = 0; ni < 8; ni++) {
                int col = n0 + nBase + ni * 8 + tig * 2;
                if (sizeof(TOut) == 2) {
                    __half2 v0; v0.x = __float2half(acc[mi][ni][0]); v0.y = __float2half(acc[mi][ni][1]);
                    __half2 v1; v1.x = __float2half(acc[mi][ni][2]); v1.y = __float2half(acc[mi][ni][3]);
                    if (r0 < Mvalid) *(__half2*)((__half*)Y + (size_t)r0 * NPIX_ + col) = v0;
                    if (r1 < Mvalid) *(__half2*)((__half*)Y + (size_t)r1 * NPIX_ + col) = v1;
                } else {
                    if (r0 < Mvalid) *(float2*)((float*)Y + (size_t)r0 * NPIX_ + col) = make_float2(acc[mi][ni][0], acc[mi][ni][1]);
                    if (r1 < Mvalid) *(float2*)((float*)Y + (size_t)r1 * NPIX_ + col) = make_float2(acc[mi][ni][2], acc[mi][ni][3]);
                }
            }
        }
    }
}

// ---------------- depthwise 3x3 (fp16 in/out, fp32 compute), vectorized staging ----------------
#define TR_ 64
__global__ void dwconv_kernel(const __half* __restrict__ in,
                              const float* __restrict__ wgt,
                              __half* __restrict__ out,
                              float* __restrict__ ss) {
    __shared__ float s[TR_ + 2][HW_];
    __shared__ float red[8];
    int t = threadIdx.x;
    int ch = blockIdx.y, b = blockIdx.z;
    int y0 = blockIdx.x * TR_;
    const __half* src = in + ((size_t)b * C3_ + ch) * NPIX_;
    __half* dst = out + ((size_t)b * C3_ + ch) * NPIX_;
    float kw[9];
#pragma unroll
    for (int i = 0; i < 9; i++) kw[i] = wgt[ch * 9 + i];

    for (int i8 = t; i8 < (TR_ + 2) * 16; i8 += 256) {
        int r = i8 >> 4, c8 = i8 & 15;
        int y = y0 - 1 + r;
        float4 lo = make_float4(0.f, 0.f, 0.f, 0.f), hi = lo;
        if (y >= 0 && y < HW_) {
            uint4 raw = *(const uint4*)(src + y * HW_ + c8 * 8);
            h8_to_f8(raw, lo, hi);
        }
        *(float4*)(&s[r][c8 * 8])     = lo;
        *(float4*)(&s[r][c8 * 8 + 4]) = hi;
    }
    __syncthreads();

    float ssum = 0.f;
    for (int p4 = t; p4 < TR_ * 32; p4 += 256) {
        int r = p4 >> 5, c4 = p4 & 31;
        int col = c4 * 4;
        __half o[4];
#pragma unroll
        for (int px = 0; px < 4; px++) {
            int cc = col + px;
            float acc = 0.f;
            bool cl = cc > 0, cr = cc < HW_ - 1;
#pragma unroll
            for (int dy = 0; dy < 3; dy++) {
                const float* row = s[r + dy];
                if (cl) acc += row[cc - 1] * kw[dy * 3 + 0];
                acc += row[cc] * kw[dy * 3 + 1];
                if (cr) acc += row[cc + 1] * kw[dy * 3 + 2];
            }
            o[px] = __float2half(acc);
            float hv = __half2float(o[px]);
            ssum += hv * hv;
        }
        *(uint2*)(dst + (y0 + r) * HW_ + col) = *(uint2*)o;
    }

    if (ch < 2 * C_) {
#pragma unroll
        for (int o2 = 16; o2 > 0; o2 >>= 1) ssum += __shfl_down_sync(0xffffffffu, ssum, o2);
        if ((t & 31) == 0) red[t >> 5] = ssum;
        __syncthreads();
        if (t == 0) {
            float tot = 0.f;
#pragma unroll
            for (int i = 0; i < 8; i++) tot += red[i];
            ss[(b * 2 * C_ + ch) * 2 + blockIdx.x] = tot;
        }
    }
}

// ---------------- Gram partials (fp16 input, fp32 compute, vectorized staging) ----------------
__global__ void gram_partial(const __half* __restrict__ qkv2, float* __restrict__ gpart) {
    extern __shared__ float gsm[];
    int t = threadIdx.x;
    int grp = t >> 6, lt = t & 63;
    int h = blockIdx.y, b = blockIdx.z;
    int gi = blockIdx.x * 4 + grp;
    float* qs = gsm + grp * (2 * HD_ * GROW_);
    float* ks = qs + HD_ * GROW_;
    const __half* qb = qkv2 + ((size_t)b * C3_ + h * HD_) * NPIX_;
    const __half* kb = qkv2 + ((size_t)b * C3_ + C_ + h * HD_) * NPIX_;
    int i = lt >> 3, j = lt & 7;

    float acc[3][3];
#pragma unroll
    for (int r = 0; r < 3; r++)
#pragma unroll
        for (int s2 = 0; s2 < 3; s2++) acc[r][s2] = 0.f;

    for (int chk = 0; chk < 8; chk++) {
        int n0 = gi * 1024 + chk * 128;
        __syncthreads();
        for (int idx = lt; idx < HD_ * 16; idx += 64) {
            int c = idx >> 4, v8 = idx & 15;
            uint4 rq = *(const uint4*)(qb + (size_t)c * NPIX_ + n0 + v8 * 8);
            uint4 rk = *(const uint4*)(kb + (size_t)c * NPIX_ + n0 + v8 * 8);
            float4 qlo, qhi, klo, khi;
            h8_to_f8(rq, qlo, qhi);
            h8_to_f8(rk, klo, khi);
            *(float4*)(qs + c * GROW_ + v8 * 8)     = qlo;
            *(float4*)(qs + c * GROW_ + v8 * 8 + 4) = qhi;
            *(float4*)(ks + c * GROW_ + v8 * 8)     = klo;
            *(float4*)(ks + c * GROW_ + v8 * 8 + 4) = khi;
        }
        __syncthreads();
        const float* q0 = qs + (3 * i) * GROW_;
        const float* k0 = ks + (3 * j) * GROW_;
#pragma unroll 4
        for (int nn = 0; nn < 128; nn += 4) {
            float4 qv[3], kv[3];
#pragma unroll
            for (int r = 0; r < 3; r++) {
                qv[r] = *(const float4*)(q0 + r * GROW_ + nn);
                kv[r] = *(const float4*)(k0 + r * GROW_ + nn);
            }
#pragma unroll
            for (int r = 0; r < 3; r++)
#pragma unroll
                for (int s2 = 0; s2 < 3; s2++)
                    acc[r][s2] += qv[r].x * kv[s2].x + qv[r].y * kv[s2].y
                                + qv[r].z * kv[s2].z + qv[r].w * kv[s2].w;
        }
    }

    float* outp = gpart + (((size_t)(b * HEADS_ + h)) * GSLICES_ + gi) * (HD_ * HD_);
#pragma unroll
    for (int r = 0; r < 3; r++)
#pragma unroll
        for (int s2 = 0; s2 < 3; s2++)
            outp[(3 * i + r) * HD_ + 3 * j + s2] = acc[r][s2];
}

// ---------------- reduce partials + rnorm scale + softmax ----------------
__global__ void softmax_kernel(const float* __restrict__ gpart,
                               const float* __restrict__ ss,
                               float* __restrict__ attn) {
    int h = blockIdx.x, b = blockIdx.y;
    int t = threadIdx.x;
    int c = t / HD_, d = t - c * HD_;
    __shared__ float rq[HD_], rk[HD_];
    __shared__ float S[HD_][HD_ + 1];
    if (t < HD_) {
        const float* p = ss + (b * 2 * C_ + h * HD_ + t) * 2;
        rq[t] = 1.f / fmaxf(sqrtf(p[0] + p[1]), 1e-12f);
    } else if (t < 2 * HD_) {
        int d2 = t - HD_;
        const float* p = ss + (b * 2 * C_ + C_ + h * HD_ + d2) * 2;
        rk[d2] = 1.f / fmaxf(sqrtf(p[0] + p[1]), 1e-12f);
    }
    const float* gp = gpart + ((size_t)(b * HEADS_ + h)) * GSLICES_ * (HD_ * HD_) + t;
    float acc = 0.f;
#pragma unroll
    for (int sidx = 0; sidx < GSLICES_; sidx++) acc += gp[(size_t)sidx * (HD_ * HD_)];
    __syncthreads();
    S[c][d] = acc * rq[c] * rk[d] * 0.20412414523193154f;
    __syncthreads();
    if (d == 0) {
        float m = -1e30f;
        for (int jj = 0; jj < HD_; jj++) m = fmaxf(m, S[c][jj]);
        float sse = 0.f;
        for (int jj = 0; jj < HD_; jj++) { float e = expf(S[c][jj] - m); S[c][jj] = e; sse += e; }
        float inv = 1.f / sse;
        for (int jj = 0; jj < HD_; jj++) S[c][jj] *= inv;
    }
    __syncthreads();
    attn[(((size_t)b * HEADS_ + h) * HD_ + c) * HD_ + d] = S[c][d];
}

// ---------------- out = (attn @ v) * gate -> transposed fp16 (coalesced) ----------------
__global__ void av_kernel(const __half* __restrict__ qkv2,
                          const float* __restrict__ attn,
                          const float* __restrict__ gates,
                          uint32_t* __restrict__ ot) {
    int n0 = blockIdx.x * 256;
    int n = n0 + threadIdx.x;
    int h = blockIdx.y, b = blockIdx.z;
    __shared__ float A[HD_][HD_];
    __shared__ uint32_t sh[256][13];
    const float* ab = attn + ((size_t)b * HEADS_ + h) * HD_ * HD_;
    for (int i = threadIdx.x; i < HD_ * HD_; i += 256) A[i / HD_][i % HD_] = ab[i];
    __syncthreads();
    const __half* v = qkv2 + ((size_t)b * C3_ + 2 * C_ + h * HD_) * NPIX_ + n;
    float acc[HD_];
#pragma unroll
    for (int c = 0; c < HD_; c++) acc[c] = 0.f;
#pragma unroll
    for (int d = 0; d < HD_; d++) {
        float vv = __half2float(v[(size_t)d * NPIX_]);
#pragma unroll
        for (int c = 0; c < HD_; c++) acc[c] += A[c][d] * vv;
    }
    float g = gates[((size_t)b * HEADS_ + h) * NPIX_ + n];
#pragma unroll
    for (int c2 = 0; c2 < 12; c2++) {
        __half2 hp;
        hp.x = __float2half(acc[2 * c2] * g);
        hp.y = __float2half(acc[2 * c2 + 1] * g);
        sh[threadIdx.x][c2] = *(uint32_t*)&hp;
    }
    __syncthreads();
    for (int i = threadIdx.x; i < 256 * 12; i += 256) {
        int p = i / 12, c2 = i - p * 12;
        ot[((size_t)b * NPIX_ + n0 + p) * 96 + h * 12 + c2] = sh[p][c2];
    }
}

// ---------------- launch ----------------
extern "C" void kernel_launch(void* const* d_in, const int* in_sizes, int n_in,
                              void* d_out, int out_size) {
    const float* x       = (const float*)d_in[0];
    const float* qkv_w   = (const float*)d_in[1];
    const float* dw_w    = (const float*)d_in[2];
    const float* proj_w  = (const float*)d_in[3];
    const float* rw_main = (const float*)d_in[4];
    const float* rw_aux  = (const float*)d_in[5];
    const int*   task_id = (const int*)d_in[6];
    float* out = (float*)d_out;

    float *gates, *ss, *gpart, *attn;
    __half *qkv, *qkv2, *xt, *ot, *wq, *wp;
    cudaGetSymbolAddress((void**)&qkv,   g_qkv);
    cudaGetSymbolAddress((void**)&qkv2,  g_qkv2);
    cudaGetSymbolAddress((void**)&gates, g_gates);
    cudaGetSymbolAddress((void**)&ss,    g_ss);
    cudaGetSymbolAddress((void**)&gpart, g_gram_part);
    cudaGetSymbolAddress((void**)&attn,  g_attn);
    cudaGetSymbolAddress((void**)&xt,    g_xt);
    cudaGetSymbolAddress((void**)&ot,    g_ot);
    cudaGetSymbolAddress((void**)&wq,    g_wq);
    cudaGetSymbolAddress((void**)&wp,    g_wp);

    cudaFuncSetAttribute(gemm_mma<__half>, cudaFuncAttributeMaxDynamicSharedMemorySize, SM_GEMM_);
    cudaFuncSetAttribute(gemm_mma<float>,  cudaFuncAttributeMaxDynamicSharedMemorySize, SM_GEMM_);
    cudaFuncSetAttribute(gram_partial, cudaFuncAttributeMaxDynamicSharedMemorySize, GSM_GRAM_);

    conv_w_kernel<<<(640 * K_ + 255) / 256, 256>>>(qkv_w, wq, C3_ * K_, 640 * K_);
    conv_w_kernel<<<(256 * K_ + 255) / 256, 256>>>(proj_w, wp, C_ * K_, 256 * K_);
    fused_tr_router<<<dim3(NPIX_ / 32, B_), 256>>>(x, rw_main, rw_aux, task_id, xt, gates);
    // qkv (fp16): 5 m-tiles of 128 (last half-valid), BN=256
    gemm_mma<__half><<<dim3(NPIX_ / BN_, 1, B_), 256, SM_GEMM_>>>(wq, xt, qkv, 5, C3_);
    dwconv_kernel<<<dim3(HW_ / TR_, C3_, B_), 256>>>(qkv, dw_w, qkv2, ss);
    gram_partial<<<dim3(4, HEADS_, B_), 256, GSM_GRAM_>>>(qkv2, gpart);
    softmax_kernel<<<dim3(HEADS_, B_), 576>>>(gpart, ss, attn);
    av_kernel<<<dim3(NPIX_ / 256, HEADS_, B_), 256>>>(qkv2, attn, gates, (uint32_t*)ot);
    // out (fp32): 2 m-tiles of 128 (last half-valid)
    gemm_mma<float><<<dim3(NPIX_ / BN_, 1, B_), 256, SM_GEMM_>>>(wp, ot, out, 2, C_);
}

// round 17
// speedup vs baseline: 1.1047x; 1.1047x over previous
#include <cuda_runtime.h>
#include <cuda_fp16.h>
#include <math.h>
#include <stdint.h>

#define B_     8
#define C_     192
#define HEADS_ 8
#define HD_    24
#define HW_    128
#define NPIX_  16384
#define C3_    576
#define K_     192

// GEMM tiling (R14 config): 1-pass fp16, BM=64 (dbuf A), BN=256, warp tile 32x64
#define BN_ 256
#define BMq_ 64
#define BT_ROW_ 400
#define BTILE_ (BN_ * BT_ROW_)     // 102400
#define ATILE_ (BMq_ * BT_ROW_)    // 25600
#define SM_GEMM_ (BTILE_ + 2 * ATILE_)   // 153600

// gram (HMMA): 4 warps/block, per-warp panels, 24/32 rows x 264 halves
#define GPARTS_ 32                 // 8 slices x 4 warps
#define GW_ROW_ 264                // halves per row (528B, stride 33*16B -> conflict-free)
#define GW_Q_ (32 * GW_ROW_ * 2)   // 16896 B
#define GW_K_ (24 * GW_ROW_ * 2)   // 12672 B
#define GW_PANEL_ (GW_Q_ + GW_K_)  // 29568 B
#define SM_GRAM_ (4 * GW_PANEL_)   // 118272 B

// ---------------- scratch ----------------
__device__ __half g_qkv [(size_t)B_ * C3_ * NPIX_];
__device__ __half g_qkv2[(size_t)B_ * C3_ * NPIX_];
__device__ float g_gates[(size_t)B_ * HEADS_ * NPIX_];
__device__ float g_ss  [B_ * 2 * C_ * 2];
__device__ float g_gram_part[(size_t)B_ * HEADS_ * GPARTS_ * HD_ * HD_];
__device__ float g_attn [B_ * HEADS_ * HD_ * HD_];
__device__ __half g_xt  [(size_t)B_ * NPIX_ * K_];
__device__ __half g_ot  [(size_t)B_ * NPIX_ * K_];
__device__ __half g_wq  [C3_ * K_];
__device__ __half g_wp  [C_ * K_];

// ---------------- helpers ----------------
__device__ __forceinline__ uint32_t smem_u32(const void* p) {
    uint32_t a;
    asm("{ .reg .u64 t; cvta.to.shared.u64 t, %1; cvt.u32.u64 %0, t; }" : "=r"(a) : "l"(p));
    return a;
}
__device__ __forceinline__ void cp16(uint32_t d, const void* s) {
    asm volatile("cp.async.cg.shared.global [%0], [%1], 16;" :: "r"(d), "l"(s));
}
#define CP_COMMIT() asm volatile("cp.async.commit_group;" ::: "memory")
#define CP_WAIT(n)  asm volatile("cp.async.wait_group %0;" :: "n"(n) : "memory")
__device__ __forceinline__ void ldm_x4(uint32_t& r0, uint32_t& r1, uint32_t& r2, uint32_t& r3, uint32_t a) {
    asm volatile("ldmatrix.sync.aligned.m8n8.x4.shared.b16 {%0,%1,%2,%3}, [%4];"
                 : "=r"(r0), "=r"(r1), "=r"(r2), "=r"(r3) : "r"(a));
}
__device__ __forceinline__ void ldm_x2(uint32_t& r0, uint32_t& r1, uint32_t a) {
    asm volatile("ldmatrix.sync.aligned.m8n8.x2.shared.b16 {%0,%1}, [%2];"
                 : "=r"(r0), "=r"(r1) : "r"(a));
}
__device__ __forceinline__ void mma16816(float* c, uint32_t a0, uint32_t a1, uint32_t a2, uint32_t a3,
                                         uint32_t b0, uint32_t b1) {
    asm volatile("mma.sync.aligned.m16n8k16.row.col.f32.f16.f16.f32 "
                 "{%0,%1,%2,%3}, {%4,%5,%6,%7}, {%8,%9}, {%0,%1,%2,%3};"
                 : "+f"(c[0]), "+f"(c[1]), "+f"(c[2]), "+f"(c[3])
                 : "r"(a0), "r"(a1), "r"(a2), "r"(a3), "r"(b0), "r"(b1));
}
__device__ __forceinline__ void h8_to_f8(uint4 raw, float4& lo, float4& hi) {
    const __half2* hp = (const __half2*)&raw;
    float2 f0 = __half22float2(hp[0]);
    float2 f1 = __half22float2(hp[1]);
    float2 f2 = __half22float2(hp[2]);
    float2 f3 = __half22float2(hp[3]);
    lo = make_float4(f0.x, f0.y, f1.x, f1.y);
    hi = make_float4(f2.x, f2.y, f3.x, f3.y);
}

// ---------------- convert fp32 -> fp16 weights ----------------
__global__ void conv_w_kernel(const float* __restrict__ w, __half* __restrict__ o, int total) {
    int i = blockIdx.x * 256 + threadIdx.x;
    if (i < total) o[i] = __float2half(w[i]);
}

// ---------------- fused: transpose x (fp16, vectorized) AND router gates ----------------
__global__ void fused_tr_router(const float* __restrict__ x,
                                const float* __restrict__ rw_main,
                                const float* __restrict__ rw_aux,
                                const int*   __restrict__ task_id,
                                __half* __restrict__ xt,
                                float* __restrict__ gates) {
    int b = blockIdx.y;
    int n0 = blockIdx.x * 32;
    __shared__ float tile[C_][33];
    __shared__ float w[HEADS_ * C_];
    __shared__ float sg[HEADS_][32];
    int t = threadIdx.x;
    const float* rw = (task_id[0] == 0) ? rw_main : rw_aux;
    for (int i = t; i < HEADS_ * C_; i += 256) w[i] = rw[i];
    for (int i = t; i < C_ * 32; i += 256) {
        int c = i >> 5, j = i & 31;
        tile[c][j] = x[((size_t)b * C_ + c) * NPIX_ + n0 + j];
    }
    __syncthreads();

    for (int i = t; i < 32 * 24; i += 256) {
        int j = i / 24, c8 = i - j * 24;
        __half hv[8];
#pragma unroll
        for (int q = 0; q < 8; q++) hv[q] = __float2half(tile[c8 * 8 + q][j]);
        *(uint4*)(xt + ((size_t)b * NPIX_ + n0 + j) * K_ + c8 * 8) = *(uint4*)hv;
    }

    int j = t >> 3, k = t & 7;
    float lg[HEADS_];
#pragma unroll
    for (int h = 0; h < HEADS_; h++) lg[h] = 0.f;
#pragma unroll
    for (int i = 0; i < 24; i++) {
        int c = k + i * 8;
        float xv = tile[c][j];
#pragma unroll
        for (int h = 0; h < HEADS_; h++) lg[h] += xv * w[h * C_ + c];
    }
#pragma unroll
    for (int h = 0; h < HEADS_; h++) {
        lg[h] += __shfl_down_sync(0xffffffffu, lg[h], 4, 8);
        lg[h] += __shfl_down_sync(0xffffffffu, lg[h], 2, 8);
        lg[h] += __shfl_down_sync(0xffffffffu, lg[h], 1, 8);
    }
    if (k == 0) {
        float mx = lg[0];
#pragma unroll
        for (int h = 1; h < HEADS_; h++) mx = fmaxf(mx, lg[h]);
        float p[HEADS_]; float s = 0.f;
#pragma unroll
        for (int h = 0; h < HEADS_; h++) { p[h] = expf(lg[h] - mx); s += p[h]; }
        float inv = 1.f / s;
#pragma unroll
        for (int h = 0; h < HEADS_; h++) p[h] *= inv;
        int h1 = 0;
#pragma unroll
        for (int h = 1; h < HEADS_; h++) if (p[h] > p[h1]) h1 = h;
        int h2 = -1;
#pragma unroll
        for (int h = 0; h < HEADS_; h++) if (h != h1 && (h2 < 0 || p[h] > p[h2])) h2 = h;
        float denom = fmaxf(p[h1] + p[h2], 1.1920929e-07f);
        float gscale = 2.0f / denom;
#pragma unroll
        for (int h = 0; h < HEADS_; h++)
            sg[h][j] = (h == h1) ? p[h1] * gscale : ((h == h2) ? p[h2] * gscale : 0.f);
    }
    __syncthreads();
    {
        int h = t >> 5, jj = t & 31;
        gates[((size_t)b * HEADS_ + h) * NPIX_ + n0 + jj] = sg[h][jj];
    }
}

// ---------------- HMMA fp16 1-pass GEMM (R14): BM=64 dbuf A, BN=256, warp 32x64 ----------------
template<typename TOut>
__global__ void __launch_bounds__(256, 1)
gemm_mma(const __half* __restrict__ A,
         const __half* __restrict__ Bx,
         TOut* __restrict__ Y, int mtiles) {
    extern __shared__ char dsm[];
    uint32_t sb = smem_u32(dsm);
    uint32_t uB = sb;
    uint32_t uA = sb + BTILE_;

    int t = threadIdx.x, wid = t >> 5, lane = t & 31;
    int n0 = blockIdx.x * BN_;
    int b  = blockIdx.z;
    int Mvalid = mtiles * BMq_;
    Y += (size_t)b * Mvalid * NPIX_;

    const char* pB = (const char*)(Bx + ((size_t)b * NPIX_ + n0) * K_);
    for (int i = t; i < 6144; i += 256) {
        int r = i / 24, ck = i - r * 24;
        cp16(uB + r * BT_ROW_ + ck * 16, pB + i * 16);
    }
    for (int i = t; i < 1536; i += 256) {
        int r = i / 24, ck = i - r * 24;
        cp16(uA + r * BT_ROW_ + ck * 16, A + (size_t)r * K_ + ck * 8);
    }
    CP_COMMIT();

    int wm = wid >> 2, wn = wid & 3;
    int mBase = wm * 32;
    int nBase = wn * 64;
    uint32_t aRowOff = (mBase + (lane & 15)) * BT_ROW_ + (lane >> 4) * 16;
    uint32_t bAddr4 = (nBase + ((lane >> 4) & 1) * 8 + (lane & 7)) * BT_ROW_ + ((lane >> 3) & 1) * 16;
    int grp = lane >> 2, tig = lane & 3;

    for (int mt = 0; mt < mtiles; mt++) {
        __syncthreads();
        if (mt + 1 < mtiles) {
            int m0n = (mt + 1) * BMq_;
            uint32_t bufb = uA + ((mt + 1) & 1) * ATILE_;
            for (int i = t; i < 1536; i += 256) {
                int r = i / 24, ck = i - r * 24;
                cp16(bufb + r * BT_ROW_ + ck * 16, A + (size_t)(m0n + r) * K_ + ck * 8);
            }
            CP_COMMIT();
            CP_WAIT(1);
        } else {
            CP_WAIT(0);
        }
        __syncthreads();

        uint32_t uAh = uA + (mt & 1) * ATILE_;
        int m0 = mt * BMq_;

        float acc[2][8][4];
#pragma unroll
        for (int mi = 0; mi < 2; mi++)
#pragma unroll
            for (int ni = 0; ni < 8; ni++)
#pragma unroll
                for (int jj = 0; jj < 4; jj++) acc[mi][ni][jj] = 0.f;

#pragma unroll
        for (int kc = 0; kc < 12; kc++) {
            uint32_t kByte = kc * 32;
            uint32_t ah[2][4], bh[8][2];
#pragma unroll
            for (int mi = 0; mi < 2; mi++) {
                uint32_t o = aRowOff + mi * (16 * BT_ROW_) + kByte;
                ldm_x4(ah[mi][0], ah[mi][1], ah[mi][2], ah[mi][3], uAh + o);
            }
#pragma unroll
            for (int pr = 0; pr < 4; pr++) {
                uint32_t o = bAddr4 + pr * (16 * BT_ROW_) + kByte;
                ldm_x4(bh[pr*2][0], bh[pr*2][1], bh[pr*2+1][0], bh[pr*2+1][1], uB + o);
            }
#pragma unroll
            for (int mi = 0; mi < 2; mi++)
#pragma unroll
                for (int ni = 0; ni < 8; ni++)
                    mma16816(acc[mi][ni], ah[mi][0], ah[mi][1], ah[mi][2], ah[mi][3], bh[ni][0], bh[ni][1]);
        }

#pragma unroll
        for (int mi = 0; mi < 2; mi++) {
            int r0 = m0 + mBase + mi * 16 + grp;
            int r1 = r0 + 8;
#pragma unroll
            for (int ni = 0; ni < 8; ni++) {
                int col = n0 + nBase + ni * 8 + tig * 2;
                if (sizeof(TOut) == 2) {
                    __half2 v0; v0.x = __float2half(acc[mi][ni][0]); v0.y = __float2half(acc[mi][ni][1]);
                    __half2 v1; v1.x = __float2half(acc[mi][ni][2]); v1.y = __float2half(acc[mi][ni][3]);
                    *(__half2*)((__half*)Y + (size_t)r0 * NPIX_ + col) = v0;
                    *(__half2*)((__half*)Y + (size_t)r1 * NPIX_ + col) = v1;
                } else {
                    *(float2*)((float*)Y + (size_t)r0 * NPIX_ + col) = make_float2(acc[mi][ni][0], acc[mi][ni][1]);
                    *(float2*)((float*)Y + (size_t)r1 * NPIX_ + col) = make_float2(acc[mi][ni][2], acc[mi][ni][3]);
                }
            }
        }
    }
}

// ---------------- depthwise 3x3 (fp16 in/out, fp32 compute), vectorized staging ----------------
#define TR_ 64
__global__ void dwconv_kernel(const __half* __restrict__ in,
                              const float* __restrict__ wgt,
                              __half* __restrict__ out,
                              float* __restrict__ ss) {
    __shared__ float s[TR_ + 2][HW_];
    __shared__ float red[8];
    int t = threadIdx.x;
    int ch = blockIdx.y, b = blockIdx.z;
    int y0 = blockIdx.x * TR_;
    const __half* src = in + ((size_t)b * C3_ + ch) * NPIX_;
    __half* dst = out + ((size_t)b * C3_ + ch) * NPIX_;
    float kw[9];
#pragma unroll
    for (int i = 0; i < 9; i++) kw[i] = wgt[ch * 9 + i];

    for (int i8 = t; i8 < (TR_ + 2) * 16; i8 += 256) {
        int r = i8 >> 4, c8 = i8 & 15;
        int y = y0 - 1 + r;
        float4 lo = make_float4(0.f, 0.f, 0.f, 0.f), hi = lo;
        if (y >= 0 && y < HW_) {
            uint4 raw = *(const uint4*)(src + y * HW_ + c8 * 8);
            h8_to_f8(raw, lo, hi);
        }
        *(float4*)(&s[r][c8 * 8])     = lo;
        *(float4*)(&s[r][c8 * 8 + 4]) = hi;
    }
    __syncthreads();

    float ssum = 0.f;
    for (int p4 = t; p4 < TR_ * 32; p4 += 256) {
        int r = p4 >> 5, c4 = p4 & 31;
        int col = c4 * 4;
        __half o[4];
#pragma unroll
        for (int px = 0; px < 4; px++) {
            int cc = col + px;
            float acc = 0.f;
            bool cl = cc > 0, cr = cc < HW_ - 1;
#pragma unroll
            for (int dy = 0; dy < 3; dy++) {
                const float* row = s[r + dy];
                if (cl) acc += row[cc - 1] * kw[dy * 3 + 0];
                acc += row[cc] * kw[dy * 3 + 1];
                if (cr) acc += row[cc + 1] * kw[dy * 3 + 2];
            }
            o[px] = __float2half(acc);
            float hv = __half2float(o[px]);
            ssum += hv * hv;
        }
        *(uint2*)(dst + (y0 + r) * HW_ + col) = *(uint2*)o;
    }

    if (ch < 2 * C_) {
#pragma unroll
        for (int o2 = 16; o2 > 0; o2 >>= 1) ssum += __shfl_down_sync(0xffffffffu, ssum, o2);
        if ((t & 31) == 0) red[t >> 5] = ssum;
        __syncthreads();
        if (t == 0) {
            float tot = 0.f;
#pragma unroll
            for (int i = 0; i < 8; i++) tot += red[i];
            ss[(b * 2 * C_ + ch) * 2 + blockIdx.x] = tot;
        }
    }
}

// ---------------- Gram via HMMA: D = q k^T, per-warp self-contained panels ----------------
// grid (8, HEADS, B), 128 threads (4 warps). Warp w owns pixels [slice*2048 + w*512, +512)
// processed in 2 chunks of 256. M=24 padded to 32 (garbage rows never stored).
__global__ void __launch_bounds__(128, 1)
gram_mma(const __half* __restrict__ qkv2, float* __restrict__ gpart) {
    extern __shared__ char gdsm[];
    int t = threadIdx.x, w = t >> 5, lane = t & 31;
    int slice = blockIdx.x, h = blockIdx.y, b = blockIdx.z;
    char* panel = gdsm + w * GW_PANEL_;
    uint32_t uQ = smem_u32(panel);
    uint32_t uK = uQ + GW_Q_;
    __half* sq = (__half*)panel;
    __half* sk = (__half*)(panel + GW_Q_);

    const __half* qb = qkv2 + ((size_t)b * C3_ + h * HD_) * NPIX_;
    const __half* kb = qkv2 + ((size_t)b * C3_ + C_ + h * HD_) * NPIX_;
    int base = slice * 2048 + w * 512;

    float acc[2][3][4];
#pragma unroll
    for (int mi = 0; mi < 2; mi++)
#pragma unroll
        for (int nf = 0; nf < 3; nf++)
#pragma unroll
            for (int jj = 0; jj < 4; jj++) acc[mi][nf][jj] = 0.f;

    // ldmatrix lane addressing (per-warp panel base)
    uint32_t aOff = (lane & 15) * (GW_ROW_ * 2) + (lane >> 4) * 16;
    uint32_t b4Off = (((lane >> 4) & 1) * 8 + (lane & 7)) * (GW_ROW_ * 2) + ((lane >> 3) & 1) * 16;
    uint32_t b2Off = (16 + (lane & 7)) * (GW_ROW_ * 2) + ((lane >> 3) & 1) * 16;

#pragma unroll
    for (int chk = 0; chk < 2; chk++) {
        int n0 = base + chk * 256;
        __syncwarp();
        // stage q,k: 24 rows x 32 uint4 each
        for (int i = lane; i < 24 * 32; i += 32) {
            int c = i >> 5, v8 = i & 31;
            *(uint4*)(sq + c * GW_ROW_ + v8 * 8) = *(const uint4*)(qb + (size_t)c * NPIX_ + n0 + v8 * 8);
            *(uint4*)(sk + c * GW_ROW_ + v8 * 8) = *(const uint4*)(kb + (size_t)c * NPIX_ + n0 + v8 * 8);
        }
        __syncwarp();
#pragma unroll
        for (int kc = 0; kc < 16; kc++) {
            uint32_t kByte = kc * 32;
            uint32_t a0[4], a1[4], bb[3][2];
            ldm_x4(a0[0], a0[1], a0[2], a0[3], uQ + aOff + kByte);                       // rows 0-15
            ldm_x4(a1[0], a1[1], a1[2], a1[3], uQ + aOff + 16 * (GW_ROW_ * 2) + kByte);  // rows 16-31 (24+ garbage)
            ldm_x4(bb[0][0], bb[0][1], bb[1][0], bb[1][1], uK + b4Off + kByte);          // n 0-15
            ldm_x2(bb[2][0], bb[2][1], uK + b2Off + kByte);                              // n 16-23
#pragma unroll
            for (int nf = 0; nf < 3; nf++) {
                mma16816(acc[0][nf], a0[0], a0[1], a0[2], a0[3], bb[nf][0], bb[nf][1]);
                mma16816(acc[1][nf], a1[0], a1[1], a1[2], a1[3], bb[nf][0], bb[nf][1]);
            }
        }
    }

    // store 24x24 partial (part index = slice*4 + w)
    int grp = lane >> 2, tig = lane & 3;
    float* outp = gpart + (((size_t)(b * HEADS_ + h)) * GPARTS_ + slice * 4 + w) * (HD_ * HD_);
#pragma unroll
    for (int mi = 0; mi < 2; mi++) {
        int r0 = mi * 16 + grp;
        int r1 = r0 + 8;
#pragma unroll
        for (int nf = 0; nf < 3; nf++) {
            int col = nf * 8 + tig * 2;
            if (r0 < HD_) *(float2*)(outp + r0 * HD_ + col) = make_float2(acc[mi][nf][0], acc[mi][nf][1]);
            if (r1 < HD_) *(float2*)(outp + r1 * HD_ + col) = make_float2(acc[mi][nf][2], acc[mi][nf][3]);
        }
    }
}

// ---------------- reduce partials + rnorm scale + softmax ----------------
__global__ void softmax_kernel(const float* __restrict__ gpart,
                               const float* __restrict__ ss,
                               float* __restrict__ attn) {
    int h = blockIdx.x, b = blockIdx.y;
    int t = threadIdx.x;
    int c = t / HD_, d = t - c * HD_;
    __shared__ float rq[HD_], rk[HD_];
    __shared__ float S[HD_][HD_ + 1];
    if (t < HD_) {
        const float* p = ss + (b * 2 * C_ + h * HD_ + t) * 2;
        rq[t] = 1.f / fmaxf(sqrtf(p[0] + p[1]), 1e-12f);
    } else if (t < 2 * HD_) {
        int d2 = t - HD_;
        const float* p = ss + (b * 2 * C_ + C_ + h * HD_ + d2) * 2;
        rk[d2] = 1.f / fmaxf(sqrtf(p[0] + p[1]), 1e-12f);
    }
    const float* gp = gpart + ((size_t)(b * HEADS_ + h)) * GPARTS_ * (HD_ * HD_) + t;
    float acc = 0.f;
#pragma unroll
    for (int sidx = 0; sidx < GPARTS_; sidx++) acc += gp[(size_t)sidx * (HD_ * HD_)];
    __syncthreads();
    S[c][d] = acc * rq[c] * rk[d] * 0.20412414523193154f;
    __syncthreads();
    if (d == 0) {
        float m = -1e30f;
        for (int jj = 0; jj < HD_; jj++) m = fmaxf(m, S[c][jj]);
        float sse = 0.f;
        for (int jj = 0; jj < HD_; jj++) { float e = expf(S[c][jj] - m); S[c][jj] = e; sse += e; }
        float inv = 1.f / sse;
        for (int jj = 0; jj < HD_; jj++) S[c][jj] *= inv;
    }
    __syncthreads();
    attn[(((size_t)b * HEADS_ + h) * HD_ + c) * HD_ + d] = S[c][d];
}

// ---------------- out = (attn @ v) * gate -> transposed fp16 (coalesced) ----------------
__global__ void av_kernel(const __half* __restrict__ qkv2,
                          const float* __restrict__ attn,
                          const float* __restrict__ gates,
                          uint32_t* __restrict__ ot) {
    int n0 = blockIdx.x * 256;
    int n = n0 + threadIdx.x;
    int h = blockIdx.y, b = blockIdx.z;
    __shared__ float A[HD_][HD_];
    __shared__ uint32_t sh[256][13];
    const float* ab = attn + ((size_t)b * HEADS_ + h) * HD_ * HD_;
    for (int i = threadIdx.x; i < HD_ * HD_; i += 256) A[i / HD_][i % HD_] = ab[i];
    __syncthreads();
    const __half* v = qkv2 + ((size_t)b * C3_ + 2 * C_ + h * HD_) * NPIX_ + n;
    float acc[HD_];
#pragma unroll
    for (int c = 0; c < HD_; c++) acc[c] = 0.f;
#pragma unroll
    for (int d = 0; d < HD_; d++) {
        float vv = __half2float(v[(size_t)d * NPIX_]);
#pragma unroll
        for (int c = 0; c < HD_; c++) acc[c] += A[c][d] * vv;
    }
    float g = gates[((size_t)b * HEADS_ + h) * NPIX_ + n];
#pragma unroll
    for (int c2 = 0; c2 < 12; c2++) {
        __half2 hp;
        hp.x = __float2half(acc[2 * c2] * g);
        hp.y = __float2half(acc[2 * c2 + 1] * g);
        sh[threadIdx.x][c2] = *(uint32_t*)&hp;
    }
    __syncthreads();
    for (int i = threadIdx.x; i < 256 * 12; i += 256) {
        int p = i / 12, c2 = i - p * 12;
        ot[((size_t)b * NPIX_ + n0 + p) * 96 + h * 12 + c2] = sh[p][c2];
    }
}

// ---------------- launch ----------------
extern "C" void kernel_launch(void* const* d_in, const int* in_sizes, int n_in,
                              void* d_out, int out_size) {
    const float* x       = (const float*)d_in[0];
    const float* qkv_w   = (const float*)d_in[1];
    const float* dw_w    = (const float*)d_in[2];
    const float* proj_w  = (const float*)d_in[3];
    const float* rw_main = (const float*)d_in[4];
    const float* rw_aux  = (const float*)d_in[5];
    const int*   task_id = (const int*)d_in[6];
    float* out = (float*)d_out;

    float *gates, *ss, *gpart, *attn;
    __half *qkv, *qkv2, *xt, *ot, *wq, *wp;
    cudaGetSymbolAddress((void**)&qkv,   g_qkv);
    cudaGetSymbolAddress((void**)&qkv2,  g_qkv2);
    cudaGetSymbolAddress((void**)&gates, g_gates);
    cudaGetSymbolAddress((void**)&ss,    g_ss);
    cudaGetSymbolAddress((void**)&gpart, g_gram_part);
    cudaGetSymbolAddress((void**)&attn,  g_attn);
    cudaGetSymbolAddress((void**)&xt,    g_xt);
    cudaGetSymbolAddress((void**)&ot,    g_ot);
    cudaGetSymbolAddress((void**)&wq,    g_wq);
    cudaGetSymbolAddress((void**)&wp,    g_wp);

    cudaFuncSetAttribute(gemm_mma<__half>, cudaFuncAttributeMaxDynamicSharedMemorySize, SM_GEMM_);
    cudaFuncSetAttribute(gemm_mma<float>,  cudaFuncAttributeMaxDynamicSharedMemorySize, SM_GEMM_);
    cudaFuncSetAttribute(gram_mma, cudaFuncAttributeMaxDynamicSharedMemorySize, SM_GRAM_);

    conv_w_kernel<<<(C3_ * K_ + 255) / 256, 256>>>(qkv_w, wq, C3_ * K_);
    conv_w_kernel<<<(C_ * K_ + 255) / 256, 256>>>(proj_w, wp, C_ * K_);
    fused_tr_router<<<dim3(NPIX_ / 32, B_), 256>>>(x, rw_main, rw_aux, task_id, xt, gates);
    // qkv (fp16): R14 config, 9 m-tiles
    gemm_mma<__half><<<dim3(NPIX_ / BN_, 1, B_), 256, SM_GEMM_>>>(wq, xt, qkv, 9);
    dwconv_kernel<<<dim3(HW_ / TR_, C3_, B_), 256>>>(qkv, dw_w, qkv2, ss);
    // gram via HMMA
    gram_mma<<<dim3(8, HEADS_, B_), 128, SM_GRAM_>>>(qkv2, gpart);
    softmax_kernel<<<dim3(HEADS_, B_), 576>>>(gpart, ss, attn);
    av_kernel<<<dim3(NPIX_ / 256, HEADS_, B_), 256>>>(qkv2, attn, gates, (uint32_t*)ot);
    // out (fp32): R14 config, 3 m-tiles
    gemm_mma<float><<<dim3(NPIX_ / BN_, 1, B_), 256, SM_GEMM_>>>(wp, ot, out, 3);
}